// round 8
// baseline (speedup 1.0000x reference)
#include <cuda_runtime.h>
#include <cuda_bf16.h>
#include <math.h>

// ---------------------------------------------------------------------------
// RPN 3D loss, GB300 (sm_103a) — round 8: ONE kernel
//
// k_main: block=(na,hr,image), thread=column.
//   phase 1 (all 9216 blocks): compacted y-overlapping GT list, IoU argmax,
//     inline CE + smooth-L1 loss, bucketed double atomics, sparse atomicMax
//     candidates for per-GT best anchor; g_assign_buf written only for
//     candidate-emitting anchors.
//   phase 2 (last retiring block only — ticket via g_counter): resolve
//     best-anchor-per-gt forcing (last-g-wins on duplicate targets) as signed
//     corrections, reduce buckets, write scalar loss, re-zero all state
//     (self-restoring: globals are zero at every kernel_launch entry).
//
// The previous grid=1 fix kernel hit the documented low-grid SM issue
// throttle (×38, vanishes at grid>=148) -> 143us. Fused here into the big
// grid so the condition never arises.
//
// gt_valid (jnp bool) arrives as int32.
// ---------------------------------------------------------------------------

#define FEAT_H 32
#define FEAT_W 110
#define NA 36
#define NB 8
#define NG 32
#define A_TOTAL (FEAT_H * FEAT_W * NA)   // 126720
#define STRIDEF 16.0f
#define NBUCKET 64
#define NBLK (NA * FEAT_H * NB)          // 9216

__device__ unsigned long long g_best[NB * NG];   // (iou_bits<<32)|(~anchor)
__device__ int g_assign_buf[NB * A_TOTAL];       // agt | fg<<8 | bg<<9 (pre-force)
__device__ double g_acc2[5 * NBUCKET];           // ce, n_act, n_fg, l2, l3
__device__ unsigned g_counter;

__device__ __forceinline__ float smooth_l1(float x) {
    float ax = fabsf(x);
    return ax < 1.0f ? 0.5f * ax * ax : ax - 0.5f;
}

// smooth-L1 2D/3D regression loss for anchor a against gt agt (image b).
// MUST be the single shared implementation: phase-2 corrections subtract
// phase-1 contributions and rely on bitwise-identical recomputation.
__device__ __forceinline__ void reg_loss(
    int a, int agt, int b,
    const float* __restrict__ b2, const float* __restrict__ b3,
    const float* __restrict__ gtb, const float* __restrict__ gt3,
    const float* __restrict__ anc, const float* __restrict__ mn,
    const float* __restrict__ sd, float& l2, float& l3)
{
    int na = a % NA;
    int hw = a / NA;
    int wc = hw % FEAT_W;
    int hr = hw / FEAT_W;
    const float* an = anc + na * 9;
    float sx = wc * STRIDEF, sy = hr * STRIDEF;
    float x1 = sx + __ldg(an + 0), y1 = sy + __ldg(an + 1);
    float x2 = sx + __ldg(an + 2), y2 = sy + __ldg(an + 3);
    float w  = x2 - x1 + 1.0f, h = y2 - y1 + 1.0f;
    float cx = x1 + 0.5f * w,  cy = y1 + 0.5f * h;

    const float* gb = gtb + (b * NG + agt) * 4;
    const float* g3 = gt3 + (b * NG + agt) * 7;
    float gx1 = __ldg(gb + 0), gy1 = __ldg(gb + 1);
    float gx2 = __ldg(gb + 2), gy2 = __ldg(gb + 3);
    float gw = gx2 - gx1 + 1.0f, gh = gy2 - gy1 + 1.0f;
    float gcx = gx1 + 0.5f * gw, gcy = gy1 + 0.5f * gh;

    float t2[4], t3[7];
    t2[0] = (gcx - cx) / w;
    t2[1] = (gcy - cy) / h;
    t2[2] = logf(gw / w);
    t2[3] = logf(gh / h);
    t3[0] = (__ldg(g3 + 0) - cx) / w;
    t3[1] = (__ldg(g3 + 1) - cy) / h;
    t3[2] = __ldg(g3 + 2) - __ldg(an + 4);
    t3[3] = logf(__ldg(g3 + 3) / __ldg(an + 5));
    t3[4] = logf(__ldg(g3 + 4) / __ldg(an + 6));
    t3[5] = logf(__ldg(g3 + 5) / __ldg(an + 7));
    t3[6] = __ldg(g3 + 6) - __ldg(an + 8);

    const float4 p2 = __ldg(reinterpret_cast<const float4*>(b2) + b * A_TOTAL + a);
    float p2a[4] = {p2.x, p2.y, p2.z, p2.w};
    l2 = 0.0f; l3 = 0.0f;
    #pragma unroll
    for (int i = 0; i < 4; ++i) {
        float tv = (t2[i] - __ldg(mn + i)) / __ldg(sd + i);
        l2 += smooth_l1(p2a[i] - tv);
    }
    const float* p3 = b3 + (size_t)(b * A_TOTAL + a) * 7;
    #pragma unroll
    for (int i = 0; i < 7; ++i) {
        float tv = (t3[i] - __ldg(mn + 4 + i)) / __ldg(sd + 4 + i);
        l3 += smooth_l1(__ldg(p3 + i) - tv);
    }
}

__device__ __forceinline__ float lse4(float4 c) {
    float m = fmaxf(fmaxf(c.x, c.y), fmaxf(c.z, c.w));
    float se = __expf(c.x - m) + __expf(c.y - m) + __expf(c.z - m) + __expf(c.w - m);
    return m + __logf(se);
}

__device__ __forceinline__ float sel4(float4 c, int lbl) {
    return (lbl == 0) ? c.x : (lbl == 1) ? c.y : (lbl == 2) ? c.z : c.w;
}

// ------------------------------- k_main ------------------------------------
__global__ __launch_bounds__(128) void k_main(
    const float* __restrict__ cls,       // [B,A,4]
    const float* __restrict__ b2,        // [B,A,4]
    const float* __restrict__ b3,        // [B,A,7]
    const float* __restrict__ gtb,       // [B,G,4]
    const float* __restrict__ gt3,       // [B,G,7]
    const int*   __restrict__ glbl,      // [B,G]
    const int*   __restrict__ gval,      // [B,G]
    const float* __restrict__ anc,       // [NA,9]
    const float* __restrict__ mn,        // [1,11]
    const float* __restrict__ sd,        // [1,11]
    float* __restrict__ out)
{
    __shared__ float4 s_g4[NG];          // {gx1, gx2+1, ag, ih}
    __shared__ int    s_gidx[NG];
    __shared__ int    s_cnt, s_any;
    __shared__ float  s_red[4][5];
    __shared__ unsigned s_rank;

    int b  = blockIdx.y;
    int na = blockIdx.x % NA;
    int hr = blockIdx.x / NA;
    int t  = threadIdx.x;

    const float* an = anc + na * 9;
    float ax1 = __ldg(an + 0), ay1 = __ldg(an + 1);
    float ax2 = __ldg(an + 2), ay2 = __ldg(an + 3);
    float sy  = hr * STRIDEF;
    float y1  = sy + ay1, y2p = sy + ay2 + 1.0f;
    float hgt = y2p - y1;

    if (t < 32) {                        // warp 0: gt preprocessing + compaction
        const float* gb = gtb + (b * NG + t) * 4;
        float gx1 = gb[0], gy1 = gb[1], gx2 = gb[2], gy2 = gb[3];
        int v = (gval[b * NG + t] != 0);
        float ih = fminf(y2p, gy2 + 1.0f) - fmaxf(y1, gy1);
        ih = fmaxf(ih, 0.0f);
        int act = v && (ih > 0.0f);
        unsigned mact = __ballot_sync(0xFFFFFFFFu, act);
        unsigned mval = __ballot_sync(0xFFFFFFFFu, v);
        if (act) {
            int pos = __popc(mact & ((1u << t) - 1u));
            s_g4[pos] = make_float4(gx1, gx2 + 1.0f,
                                    (gx2 - gx1 + 1.0f) * (gy2 - gy1 + 1.0f), ih);
            s_gidx[pos] = t;
        }
        if (t == 0) { s_cnt = __popc(mact); s_any = (mval != 0u); }
    }
    __syncthreads();

    int  valid_t = (t < FEAT_W);
    int  cnt = s_cnt;
    int  a = (hr * FEAT_W + t) * NA + na;

    float sx  = t * STRIDEF;
    float x1  = sx + ax1, x2p = sx + ax2 + 1.0f;
    float ar  = (x2p - x1) * hgt;

    float bestI = -1.0f, bestU = 1.0f;
    int bestJ = 0;
    int emitted = 0;
    int gbase = b * NG;

    #pragma unroll 2
    for (int j = 0; j < cnt; ++j) {
        float4 q = s_g4[j];
        float iw = fminf(x2p, q.y) - fmaxf(x1, q.x);
        iw = fmaxf(iw, 0.0f);
        float inter = iw * q.w;
        float uni   = (ar + q.z) - inter;
        if (inter * bestU > bestI * uni) { bestI = inter; bestU = uni; bestJ = j; }
        if (valid_t && inter >= 0.3489f * uni) {   // widened; exact test in phase 2
            float iou = inter / uni;
            unsigned long long pk =
                (((unsigned long long)__float_as_uint(iou)) << 32) |
                (unsigned long long)(0xFFFFFFFFu - (unsigned)a);
            atomicMax(&g_best[gbase + s_gidx[j]], pk);
            emitted = 1;
        }
    }

    int fg0 = 0, bgc = 0, agt = 0;
    float r_ce = 0.0f, r_l2 = 0.0f, r_l3 = 0.0f;
    if (valid_t) {
        float q = bestI / bestU;                   // IEEE div, as reference
        fg0 = (cnt > 0) && (q >= 0.5f);
        bgc = (!fg0) && s_any;
        agt = (cnt > 0) ? s_gidx[bestJ] : 0;
        // only candidate-emitting anchors can be read in phase 2
        if (emitted)
            g_assign_buf[b * A_TOTAL + a] = agt | (fg0 << 8) | (bgc << 9);

        if (fg0 | bgc) {
            const float4 c = __ldg(reinterpret_cast<const float4*>(cls) + b * A_TOTAL + a);
            int lbl = fg0 ? __ldg(&glbl[b * NG + agt]) : 0;
            r_ce = lse4(c) - sel4(c, lbl);
        }
        if (fg0)
            reg_loss(a, agt, b, b2, b3, gtb, gt3, anc, mn, sd, r_l2, r_l3);
    }

    // block reduce -> bucketed atomics
    unsigned ba_act = __ballot_sync(0xFFFFFFFFu, fg0 | bgc);
    unsigned ba_fg  = __ballot_sync(0xFFFFFFFFu, fg0);
    #pragma unroll
    for (int off = 16; off; off >>= 1)
        r_ce += __shfl_down_sync(0xFFFFFFFFu, r_ce, off);
    if (ba_fg) {
        #pragma unroll
        for (int off = 16; off; off >>= 1) {
            r_l2 += __shfl_down_sync(0xFFFFFFFFu, r_l2, off);
            r_l3 += __shfl_down_sync(0xFFFFFFFFu, r_l3, off);
        }
    }
    int wid = t >> 5, lane = t & 31;
    if (lane == 0) {
        s_red[wid][0] = r_ce;
        s_red[wid][1] = (float)__popc(ba_act);
        s_red[wid][2] = (float)__popc(ba_fg);
        s_red[wid][3] = r_l2;
        s_red[wid][4] = r_l3;
    }
    __syncthreads();
    if (t == 0) {
        float u0 = 0, u1 = 0, u2 = 0, u3 = 0, u4 = 0;
        #pragma unroll
        for (int wv = 0; wv < 4; ++wv) {
            u0 += s_red[wv][0]; u1 += s_red[wv][1]; u2 += s_red[wv][2];
            u3 += s_red[wv][3]; u4 += s_red[wv][4];
        }
        int bucket = (blockIdx.x + blockIdx.y * 8) & (NBUCKET - 1);
        atomicAdd(&g_acc2[0 * NBUCKET + bucket], (double)u0);
        atomicAdd(&g_acc2[1 * NBUCKET + bucket], (double)u1);
        atomicAdd(&g_acc2[2 * NBUCKET + bucket], (double)u2);
        if (u2 > 0.0f) {
            atomicAdd(&g_acc2[3 * NBUCKET + bucket], (double)u3);
            atomicAdd(&g_acc2[4 * NBUCKET + bucket], (double)u4);
        }
    }

    // ---------------- phase 2: last retiring block does the fix-up ----------
    __threadfence();
    if (t == 0) s_rank = atomicAdd(&g_counter, 1u);
    __syncthreads();
    if (s_rank != NBLK - 1) return;
    __threadfence();                      // acquire side

    __shared__ int      s_forced[NB * NG];
    __shared__ unsigned s_ba[NB * NG];
    __shared__ double   s_c[4][5];

    for (int k = t; k < NB * NG; k += 128) {
        unsigned long long pk = g_best[k];
        float iou = __uint_as_float((unsigned)(pk >> 32));
        s_ba[k] = 0xFFFFFFFFu - (unsigned)(pk & 0xFFFFFFFFull);
        s_forced[k] = (gval[k] != 0) && (iou >= 0.35f);
    }
    __syncthreads();

    double dc0 = 0, dc1 = 0, dc2 = 0, dc3 = 0, dc4 = 0;
    for (int k = t; k < NB * NG; k += 128) {
        int bb = k >> 5, g = k & 31;
        // winner = forced and no higher g (same image) targets the same anchor
        int winner = s_forced[k];
        if (winner) {
            unsigned myba = s_ba[k];
            for (int gp = g + 1; gp < NG; ++gp) {
                int idx = (k & ~31) | gp;
                if (s_forced[idx] && s_ba[idx] == myba) { winner = 0; break; }
            }
        }
        if (winner) {
            int aa = (int)s_ba[k];
            int pko  = g_assign_buf[bb * A_TOTAL + aa];
            int fg_o = (pko >> 8) & 1;
            int bg_o = (pko >> 9) & 1;
            int agt_o = pko & 0xFF;

            const float4 c = __ldg(reinterpret_cast<const float4*>(cls) + bb * A_TOTAL + aa);
            float lse = lse4(c);
            int lbl_n = __ldg(&glbl[bb * NG + g]);
            int lbl_o = fg_o ? __ldg(&glbl[bb * NG + agt_o]) : 0;
            float ce_n = lse - sel4(c, lbl_n);
            float ce_o = (fg_o | bg_o) ? (lse - sel4(c, lbl_o)) : 0.0f;
            dc0 += (double)ce_n - (double)ce_o;
            dc1 += (fg_o | bg_o) ? 0.0 : 1.0;
            dc2 += fg_o ? 0.0 : 1.0;

            float l2n, l3n;
            reg_loss(aa, g, bb, b2, b3, gtb, gt3, anc, mn, sd, l2n, l3n);
            dc3 += l2n; dc4 += l3n;
            if (fg_o) {
                float l2o, l3o;
                reg_loss(aa, agt_o, bb, b2, b3, gtb, gt3, anc, mn, sd, l2o, l3o);
                dc3 -= l2o; dc4 -= l3o;
            }
        }
    }

    #pragma unroll
    for (int off = 16; off; off >>= 1) {
        dc0 += __shfl_down_sync(0xFFFFFFFFu, dc0, off);
        dc1 += __shfl_down_sync(0xFFFFFFFFu, dc1, off);
        dc2 += __shfl_down_sync(0xFFFFFFFFu, dc2, off);
        dc3 += __shfl_down_sync(0xFFFFFFFFu, dc3, off);
        dc4 += __shfl_down_sync(0xFFFFFFFFu, dc4, off);
    }
    if (lane == 0) {
        s_c[wid][0] = dc0; s_c[wid][1] = dc1; s_c[wid][2] = dc2;
        s_c[wid][3] = dc3; s_c[wid][4] = dc4;
    }
    __syncthreads();

    if (wid == 0) {
        double v[5];
        #pragma unroll
        for (int i = 0; i < 5; ++i) {
            v[i] = g_acc2[i * NBUCKET + lane] + g_acc2[i * NBUCKET + 32 + lane];
            if (lane < 4) v[i] += s_c[lane][i];
        }
        #pragma unroll
        for (int i = 0; i < 5; ++i)
            #pragma unroll
            for (int off = 16; off; off >>= 1)
                v[i] += __shfl_down_sync(0xFFFFFFFFu, v[i], off);
        if (lane == 0) {
            double nact = v[1] > 1.0 ? v[1] : 1.0;
            double nfg  = v[2] > 1.0 ? v[2] : 1.0;
            out[0] = (float)(v[0] / nact + v[3] / nfg + v[4] / nfg);
        }
    }
    __syncthreads();

    // restore invariant: all scratch zero at next kernel_launch entry
    for (int k = t; k < NB * NG; k += 128) g_best[k] = 0ull;
    for (int k = t; k < 5 * NBUCKET; k += 128) g_acc2[k] = 0.0;
    if (t == 0) g_counter = 0u;
}

extern "C" void kernel_launch(void* const* d_in, const int* in_sizes, int n_in,
                              void* d_out, int out_size) {
    const float* cls  = (const float*)d_in[0];
    const float* b2   = (const float*)d_in[1];
    const float* b3   = (const float*)d_in[2];
    const float* gtb  = (const float*)d_in[3];
    const float* gt3  = (const float*)d_in[4];
    const int*   glbl = (const int*)d_in[5];
    const int*   gval = (const int*)d_in[6];
    const float* anc  = (const float*)d_in[7];
    const float* mn   = (const float*)d_in[8];
    const float* sd   = (const float*)d_in[9];
    float* out = (float*)d_out;

    k_main<<<dim3(NA * FEAT_H, NB), 128>>>(cls, b2, b3, gtb, gt3, glbl, gval,
                                           anc, mn, sd, out);
}

// round 10
// speedup vs baseline: 6.0493x; 6.0493x over previous
#include <cuda_runtime.h>
#include <cuda_bf16.h>
#include <math.h>

// ---------------------------------------------------------------------------
// RPN 3D loss, GB300 (sm_103a) — round 9: 3 kernels, throttle-aware
//
//  k_main  : grid 9216 x 128thr. Compacted y-overlapping GT list, IoU argmax,
//            inline CE + smooth-L1, bucketed double atomics, sparse atomicMax
//            per-GT best-anchor candidates. (Round-7 phase 1; measured 7us.)
//  k_fixup : grid 256 x 32thr, one block per (image,gt). Winner resolution via
//            ballot; winner lane adds signed corrections (old contribution is
//            recomputed with the SAME inlined code -> exact cancellation).
//            >=148 CTAs active -> no single-CTA issue throttle.
//  k_final : grid 1 x 32thr, TINY body (throttle-tolerant): reduce buckets,
//            write scalar, re-zero all state (self-restoring invariant).
//
// Hard-won rule: the dynamic SM issue throttle (x38) hits any phase where only
// one CTA is active, scaling with executed body size. Serial work must be
// instruction-minimal; heavy work must be wide.
//
// gt_valid (jnp bool) arrives as int32.
// ---------------------------------------------------------------------------

#define FEAT_H 32
#define FEAT_W 110
#define NA 36
#define NB 8
#define NG 32
#define A_TOTAL (FEAT_H * FEAT_W * NA)   // 126720
#define STRIDEF 16.0f
#define NBUCKET 64

__device__ unsigned long long g_best[NB * NG];   // (iou_bits<<32)|(~anchor)
__device__ int g_assign_buf[NB * A_TOTAL];       // agt | fg<<8 | bg<<9 (pre-force)
__device__ double g_acc2[5 * NBUCKET];           // ce, n_act, n_fg, l2, l3

__device__ __forceinline__ float smooth_l1(float x) {
    float ax = fabsf(x);
    return ax < 1.0f ? 0.5f * ax * ax : ax - 0.5f;
}

// Single shared implementation: fix-up corrections rely on bitwise-identical
// recomputation of phase-1 contributions.
__device__ __forceinline__ void reg_loss(
    int a, int agt, int b,
    const float* __restrict__ b2, const float* __restrict__ b3,
    const float* __restrict__ gtb, const float* __restrict__ gt3,
    const float* __restrict__ anc, const float* __restrict__ mn,
    const float* __restrict__ sd, float& l2, float& l3)
{
    int na = a % NA;
    int hw = a / NA;
    int wc = hw % FEAT_W;
    int hr = hw / FEAT_W;
    const float* an = anc + na * 9;
    float sx = wc * STRIDEF, sy = hr * STRIDEF;
    float x1 = sx + __ldg(an + 0), y1 = sy + __ldg(an + 1);
    float x2 = sx + __ldg(an + 2), y2 = sy + __ldg(an + 3);
    float w  = x2 - x1 + 1.0f, h = y2 - y1 + 1.0f;
    float cx = x1 + 0.5f * w,  cy = y1 + 0.5f * h;

    const float* gb = gtb + (b * NG + agt) * 4;
    const float* g3 = gt3 + (b * NG + agt) * 7;
    float gx1 = __ldg(gb + 0), gy1 = __ldg(gb + 1);
    float gx2 = __ldg(gb + 2), gy2 = __ldg(gb + 3);
    float gw = gx2 - gx1 + 1.0f, gh = gy2 - gy1 + 1.0f;
    float gcx = gx1 + 0.5f * gw, gcy = gy1 + 0.5f * gh;

    float t2[4], t3[7];
    t2[0] = (gcx - cx) / w;
    t2[1] = (gcy - cy) / h;
    t2[2] = logf(gw / w);
    t2[3] = logf(gh / h);
    t3[0] = (__ldg(g3 + 0) - cx) / w;
    t3[1] = (__ldg(g3 + 1) - cy) / h;
    t3[2] = __ldg(g3 + 2) - __ldg(an + 4);
    t3[3] = logf(__ldg(g3 + 3) / __ldg(an + 5));
    t3[4] = logf(__ldg(g3 + 4) / __ldg(an + 6));
    t3[5] = logf(__ldg(g3 + 5) / __ldg(an + 7));
    t3[6] = __ldg(g3 + 6) - __ldg(an + 8);

    const float4 p2 = __ldg(reinterpret_cast<const float4*>(b2) + b * A_TOTAL + a);
    float p2a[4] = {p2.x, p2.y, p2.z, p2.w};
    l2 = 0.0f; l3 = 0.0f;
    #pragma unroll
    for (int i = 0; i < 4; ++i) {
        float tv = (t2[i] - __ldg(mn + i)) / __ldg(sd + i);
        l2 += smooth_l1(p2a[i] - tv);
    }
    const float* p3 = b3 + (size_t)(b * A_TOTAL + a) * 7;
    #pragma unroll
    for (int i = 0; i < 7; ++i) {
        float tv = (t3[i] - __ldg(mn + 4 + i)) / __ldg(sd + 4 + i);
        l3 += smooth_l1(__ldg(p3 + i) - tv);
    }
}

__device__ __forceinline__ float lse4(float4 c) {
    float m = fmaxf(fmaxf(c.x, c.y), fmaxf(c.z, c.w));
    float se = __expf(c.x - m) + __expf(c.y - m) + __expf(c.z - m) + __expf(c.w - m);
    return m + __logf(se);
}

__device__ __forceinline__ float sel4(float4 c, int lbl) {
    return (lbl == 0) ? c.x : (lbl == 1) ? c.y : (lbl == 2) ? c.z : c.w;
}

// ------------------------------- k_main ------------------------------------
__global__ __launch_bounds__(128) void k_main(
    const float* __restrict__ cls,       // [B,A,4]
    const float* __restrict__ b2,        // [B,A,4]
    const float* __restrict__ b3,        // [B,A,7]
    const float* __restrict__ gtb,       // [B,G,4]
    const float* __restrict__ gt3,       // [B,G,7]
    const int*   __restrict__ glbl,      // [B,G]
    const int*   __restrict__ gval,      // [B,G]
    const float* __restrict__ anc,       // [NA,9]
    const float* __restrict__ mn,        // [1,11]
    const float* __restrict__ sd)        // [1,11]
{
    __shared__ float4 s_g4[NG];          // {gx1, gx2+1, ag, ih}
    __shared__ int    s_gidx[NG];
    __shared__ int    s_cnt, s_any;
    __shared__ float  s_red[4][5];

    int b  = blockIdx.y;
    int na = blockIdx.x % NA;
    int hr = blockIdx.x / NA;
    int t  = threadIdx.x;

    const float* an = anc + na * 9;
    float ax1 = __ldg(an + 0), ay1 = __ldg(an + 1);
    float ax2 = __ldg(an + 2), ay2 = __ldg(an + 3);
    float sy  = hr * STRIDEF;
    float y1  = sy + ay1, y2p = sy + ay2 + 1.0f;
    float hgt = y2p - y1;

    if (t < 32) {                        // warp 0: gt preprocessing + compaction
        const float* gb = gtb + (b * NG + t) * 4;
        float gx1 = gb[0], gy1 = gb[1], gx2 = gb[2], gy2 = gb[3];
        int v = (gval[b * NG + t] != 0);
        float ih = fminf(y2p, gy2 + 1.0f) - fmaxf(y1, gy1);
        ih = fmaxf(ih, 0.0f);
        int act = v && (ih > 0.0f);
        unsigned mact = __ballot_sync(0xFFFFFFFFu, act);
        unsigned mval = __ballot_sync(0xFFFFFFFFu, v);
        if (act) {
            int pos = __popc(mact & ((1u << t) - 1u));
            s_g4[pos] = make_float4(gx1, gx2 + 1.0f,
                                    (gx2 - gx1 + 1.0f) * (gy2 - gy1 + 1.0f), ih);
            s_gidx[pos] = t;
        }
        if (t == 0) { s_cnt = __popc(mact); s_any = (mval != 0u); }
    }
    __syncthreads();

    int  valid_t = (t < FEAT_W);
    int  cnt = s_cnt;
    int  a = (hr * FEAT_W + t) * NA + na;

    float sx  = t * STRIDEF;
    float x1  = sx + ax1, x2p = sx + ax2 + 1.0f;
    float ar  = (x2p - x1) * hgt;

    float bestI = -1.0f, bestU = 1.0f;
    int bestJ = 0;
    int emitted = 0;
    int gbase = b * NG;

    #pragma unroll 2
    for (int j = 0; j < cnt; ++j) {
        float4 q = s_g4[j];
        float iw = fminf(x2p, q.y) - fmaxf(x1, q.x);
        iw = fmaxf(iw, 0.0f);
        float inter = iw * q.w;
        float uni   = (ar + q.z) - inter;
        if (inter * bestU > bestI * uni) { bestI = inter; bestU = uni; bestJ = j; }
        if (valid_t && inter >= 0.3489f * uni) {   // widened; exact test in k_fixup
            float iou = inter / uni;
            unsigned long long pk =
                (((unsigned long long)__float_as_uint(iou)) << 32) |
                (unsigned long long)(0xFFFFFFFFu - (unsigned)a);
            atomicMax(&g_best[gbase + s_gidx[j]], pk);
            emitted = 1;
        }
    }

    int fg0 = 0, bgc = 0, agt = 0;
    float r_ce = 0.0f, r_l2 = 0.0f, r_l3 = 0.0f;
    if (valid_t) {
        float q = bestI / bestU;                   // IEEE div, as reference
        fg0 = (cnt > 0) && (q >= 0.5f);
        bgc = (!fg0) && s_any;
        agt = (cnt > 0) ? s_gidx[bestJ] : 0;
        // only candidate-emitting anchors can be read by k_fixup
        if (emitted)
            g_assign_buf[b * A_TOTAL + a] = agt | (fg0 << 8) | (bgc << 9);

        if (fg0 | bgc) {
            const float4 c = __ldg(reinterpret_cast<const float4*>(cls) + b * A_TOTAL + a);
            int lbl = fg0 ? __ldg(&glbl[b * NG + agt]) : 0;
            r_ce = lse4(c) - sel4(c, lbl);
        }
        if (fg0)
            reg_loss(a, agt, b, b2, b3, gtb, gt3, anc, mn, sd, r_l2, r_l3);
    }

    // block reduce -> bucketed atomics
    unsigned ba_act = __ballot_sync(0xFFFFFFFFu, fg0 | bgc);
    unsigned ba_fg  = __ballot_sync(0xFFFFFFFFu, fg0);
    #pragma unroll
    for (int off = 16; off; off >>= 1)
        r_ce += __shfl_down_sync(0xFFFFFFFFu, r_ce, off);
    if (ba_fg) {
        #pragma unroll
        for (int off = 16; off; off >>= 1) {
            r_l2 += __shfl_down_sync(0xFFFFFFFFu, r_l2, off);
            r_l3 += __shfl_down_sync(0xFFFFFFFFu, r_l3, off);
        }
    }
    int wid = t >> 5, lane = t & 31;
    if (lane == 0) {
        s_red[wid][0] = r_ce;
        s_red[wid][1] = (float)__popc(ba_act);
        s_red[wid][2] = (float)__popc(ba_fg);
        s_red[wid][3] = r_l2;
        s_red[wid][4] = r_l3;
    }
    __syncthreads();
    if (t == 0) {
        float u0 = 0, u1 = 0, u2 = 0, u3 = 0, u4 = 0;
        #pragma unroll
        for (int wv = 0; wv < 4; ++wv) {
            u0 += s_red[wv][0]; u1 += s_red[wv][1]; u2 += s_red[wv][2];
            u3 += s_red[wv][3]; u4 += s_red[wv][4];
        }
        int bucket = (blockIdx.x + blockIdx.y * 8) & (NBUCKET - 1);
        atomicAdd(&g_acc2[0 * NBUCKET + bucket], (double)u0);
        atomicAdd(&g_acc2[1 * NBUCKET + bucket], (double)u1);
        atomicAdd(&g_acc2[2 * NBUCKET + bucket], (double)u2);
        if (u2 > 0.0f) {
            atomicAdd(&g_acc2[3 * NBUCKET + bucket], (double)u3);
            atomicAdd(&g_acc2[4 * NBUCKET + bucket], (double)u4);
        }
    }
}

// ------------------------------- k_fixup -----------------------------------
// One block per (image b, gt g). 256 blocks -> no single-CTA throttle.
__global__ __launch_bounds__(32) void k_fixup(
    const float* __restrict__ cls,
    const float* __restrict__ b2,
    const float* __restrict__ b3,
    const float* __restrict__ gtb,
    const float* __restrict__ gt3,
    const int*   __restrict__ glbl,
    const int*   __restrict__ gval,
    const float* __restrict__ anc,
    const float* __restrict__ mn,
    const float* __restrict__ sd)
{
    int blk = blockIdx.x;                // 0..255
    int b = blk >> 5, g = blk & 31;
    int l = threadIdx.x;                 // 32 lanes: lane l handles gt l of image b

    unsigned long long pk = g_best[b * NG + l];
    float iou = __uint_as_float((unsigned)(pk >> 32));
    unsigned ba = 0xFFFFFFFFu - (unsigned)(pk & 0xFFFFFFFFull);
    int forced = (gval[b * NG + l] != 0) && (iou >= 0.35f);

    unsigned my_ba   = __shfl_sync(0xFFFFFFFFu, ba, g);
    int      my_frc  = __shfl_sync(0xFFFFFFFFu, forced, g);
    // winner = forced and no higher g (same image) forces the same anchor
    unsigned same = __ballot_sync(0xFFFFFFFFu, forced && (ba == my_ba));
    int winner = my_frc && ((same >> (g + 1)) == 0u);
    if (!winner || l != 0) return;

    int aa = (int)my_ba;
    int pko   = g_assign_buf[b * A_TOTAL + aa];
    int fg_o  = (pko >> 8) & 1;
    int bg_o  = (pko >> 9) & 1;
    int agt_o = pko & 0xFF;

    const float4 c = __ldg(reinterpret_cast<const float4*>(cls) + b * A_TOTAL + aa);
    float lse = lse4(c);
    int lbl_n = __ldg(&glbl[b * NG + g]);
    int lbl_o = fg_o ? __ldg(&glbl[b * NG + agt_o]) : 0;
    float ce_n = lse - sel4(c, lbl_n);
    float ce_o = (fg_o | bg_o) ? (lse - sel4(c, lbl_o)) : 0.0f;
    double dc0 = (double)ce_n - (double)ce_o;
    double dc1 = (fg_o | bg_o) ? 0.0 : 1.0;
    double dc2 = fg_o ? 0.0 : 1.0;

    float l2n, l3n;
    reg_loss(aa, g, b, b2, b3, gtb, gt3, anc, mn, sd, l2n, l3n);
    double dc3 = l2n, dc4 = l3n;
    if (fg_o) {
        float l2o, l3o;
        reg_loss(aa, agt_o, b, b2, b3, gtb, gt3, anc, mn, sd, l2o, l3o);
        dc3 -= (double)l2o; dc4 -= (double)l3o;
    }

    int bucket = blk & (NBUCKET - 1);
    if (dc0 != 0.0) atomicAdd(&g_acc2[0 * NBUCKET + bucket], dc0);
    if (dc1 != 0.0) atomicAdd(&g_acc2[1 * NBUCKET + bucket], dc1);
    if (dc2 != 0.0) atomicAdd(&g_acc2[2 * NBUCKET + bucket], dc2);
    if (dc3 != 0.0) atomicAdd(&g_acc2[3 * NBUCKET + bucket], dc3);
    if (dc4 != 0.0) atomicAdd(&g_acc2[4 * NBUCKET + bucket], dc4);
}

// ------------------------------- k_final -----------------------------------
// grid=1 x 32 threads; body kept minimal (single-CTA issue throttle).
__global__ __launch_bounds__(32) void k_final(float* __restrict__ out) {
    int l = threadIdx.x;
    double v[5];
    #pragma unroll
    for (int i = 0; i < 5; ++i)
        v[i] = g_acc2[i * NBUCKET + l] + g_acc2[i * NBUCKET + 32 + l];
    #pragma unroll
    for (int i = 0; i < 5; ++i)
        #pragma unroll
        for (int off = 16; off; off >>= 1)
            v[i] += __shfl_down_sync(0xFFFFFFFFu, v[i], off);
    if (l == 0) {
        double nact = v[1] > 1.0 ? v[1] : 1.0;
        double nfg  = v[2] > 1.0 ? v[2] : 1.0;
        out[0] = (float)(v[0] / nact + v[3] / nfg + v[4] / nfg);
    }
    __syncwarp();
    // restore invariant: scratch zero at next kernel_launch entry
    #pragma unroll
    for (int k = l; k < NB * NG; k += 32) g_best[k] = 0ull;
    #pragma unroll
    for (int k = l; k < 5 * NBUCKET; k += 32) g_acc2[k] = 0.0;
}

extern "C" void kernel_launch(void* const* d_in, const int* in_sizes, int n_in,
                              void* d_out, int out_size) {
    const float* cls  = (const float*)d_in[0];
    const float* b2   = (const float*)d_in[1];
    const float* b3   = (const float*)d_in[2];
    const float* gtb  = (const float*)d_in[3];
    const float* gt3  = (const float*)d_in[4];
    const int*   glbl = (const int*)d_in[5];
    const int*   gval = (const int*)d_in[6];
    const float* anc  = (const float*)d_in[7];
    const float* mn   = (const float*)d_in[8];
    const float* sd   = (const float*)d_in[9];
    float* out = (float*)d_out;

    k_main<<<dim3(NA * FEAT_H, NB), 128>>>(cls, b2, b3, gtb, gt3, glbl, gval, anc, mn, sd);
    k_fixup<<<NB * NG, 32>>>(cls, b2, b3, gtb, gt3, glbl, gval, anc, mn, sd);
    k_final<<<1, 32>>>(out);
}